// round 6
// baseline (speedup 1.0000x reference)
#include <cuda_runtime.h>
#include <cstdint>

#define DI __device__ __forceinline__

static constexpr int D       = 4096;
static constexpr int ROWS    = 16384;
static constexpr int TILE_M  = 64;
static constexpr int NCTA    = ROWS / TILE_M;    // 256
static constexpr int CK      = 64;               // k-floats per chunk
static constexpr int NCHUNK  = D / CK;           // 64
static constexpr int S       = 4;                // pipeline stages

static constexpr int XROW    = CK + 4;           // 68 floats (padded row)
static constexpr int XROWB   = XROW * 4;         // 272 bytes
static constexpr int XBYTES  = TILE_M * XROWB;   // 17408
static constexpr int WBYTES  = 24 * XROWB;       // 6528
static constexpr int STG     = XBYTES + WBYTES;  // 23936 per stage
static constexpr int WOFF    = XBYTES;
static constexpr int SM_DOTS = S * STG;          // 95744
static constexpr int DSTRIDE = 25;               // 24 dots + ssq
static constexpr int SM_TOTAL = SM_DOTS + TILE_M * DSTRIDE * 4;  // 102144

static constexpr int W4      = 24 * XROW / 4;    // 408 float4 per W chunk

// g-folded weight image, chunk-grouped: [NCHUNK][24][XROW]
__device__ __align__(16) float g_Wsw[NCHUNK * 24 * XROW];

// ---------------------------------------------------------------------------
DI uint32_t smem_u32(const void* p) {
    uint32_t a;
    asm("{ .reg .u64 t; cvta.to.shared.u64 t, %1; cvt.u32.u64 %0, t; }" : "=r"(a) : "l"(p));
    return a;
}
DI void cp16(uint32_t dst, const void* src) {
    asm volatile("cp.async.cg.shared.global [%0], [%1], 16;" :: "r"(dst), "l"(src) : "memory");
}
#define CP_COMMIT() asm volatile("cp.async.commit_group;" ::: "memory")
#define CP_WAIT3()  asm volatile("cp.async.wait_group 3;" ::: "memory")

DI void ldm_x4(uint32_t& r0, uint32_t& r1, uint32_t& r2, uint32_t& r3, uint32_t addr) {
    asm volatile("ldmatrix.sync.aligned.m8n8.x4.shared.b16 {%0,%1,%2,%3}, [%4];"
                 : "=r"(r0), "=r"(r1), "=r"(r2), "=r"(r3) : "r"(addr));
}
DI void ldm_x2(uint32_t& r0, uint32_t& r1, uint32_t addr) {
    asm volatile("ldmatrix.sync.aligned.m8n8.x2.shared.b16 {%0,%1}, [%2];"
                 : "=r"(r0), "=r"(r1) : "r"(addr));
}
DI void mma_tf32(float& d0, float& d1, float& d2, float& d3,
                 uint32_t a0, uint32_t a1, uint32_t a2, uint32_t a3,
                 uint32_t b0, uint32_t b1) {
    asm volatile(
        "mma.sync.aligned.m16n8k8.row.col.f32.tf32.tf32.f32 "
        "{%0,%1,%2,%3}, {%4,%5,%6,%7}, {%8,%9}, {%0,%1,%2,%3};"
        : "+f"(d0), "+f"(d1), "+f"(d2), "+f"(d3)
        : "r"(a0), "r"(a1), "r"(a2), "r"(a3), "r"(b0), "r"(b1));
}
DI float sigmoidf_(float x) { return 1.0f / (1.0f + __expf(-x)); }

// ---------------------------------------------------------------------------
__global__ void prep_w(const float* __restrict__ Wpre, const float* __restrict__ Wpost,
                       const float* __restrict__ Wres, const float* __restrict__ g) {
    for (int idx = blockIdx.x * blockDim.x + threadIdx.x;
         idx < NCHUNK * 24 * XROW; idx += gridDim.x * blockDim.x) {
        int c   = idx / (24 * XROW);
        int rem = idx % (24 * XROW);
        int j   = rem / XROW;
        int k   = rem % XROW;
        float v = 0.0f;
        if (k < CK) {
            int kk = c * CK + k;
            float w = (j < 4)  ? Wpre[j * D + kk]
                    : (j < 8)  ? Wpost[(j - 4) * D + kk]
                    :            Wres[(j - 8) * D + kk];
            v = w * g[kk];
        }
        g_Wsw[idx] = v;
    }
}

// ---------------------------------------------------------------------------
// One CTA per 64-row tile; 8 warps = 4 m-tiles x 2 n-halves.
//   half 0: n-tiles {0,1} (cols 0..15), 2 MMA/kstep
//   half 1: n-tile {2}   (cols 16..23), 1 MMA/kstep + sum-of-squares
// Fragments via ldmatrix (f32 bits through b16 path).
// ---------------------------------------------------------------------------
__global__ void __launch_bounds__(256, 2)
mhc_main(const float* __restrict__ X,
         const float* __restrict__ b_pre, const float* __restrict__ b_post,
         const float* __restrict__ b_res,
         const float* __restrict__ alpha_pre, const float* __restrict__ alpha_post,
         const float* __restrict__ alpha_res,
         float* __restrict__ out) {
    extern __shared__ char smem[];
    float* sm = reinterpret_cast<float*>(smem);
    const uint32_t sb = smem_u32(smem);
    const int tid  = threadIdx.x;
    const int wid  = tid >> 5, lane = tid & 31;
    const int gq   = lane >> 2, cq = lane & 3;
    const int mw   = wid >> 1, h = wid & 1;
    const int wr   = mw * 16;                    // warp-pair row base in tile
    const long row0 = (long)blockIdx.x * TILE_M;
    const float* xtile = X + row0 * D;

    // ldmatrix per-lane address offsets (within a stage)
    const int lm  = lane >> 3, lr = lane & 7;
    // A: mat0 rows0-7 c0-3 | mat1 rows8-15 c0-3 | mat2 rows0-7 c4-7 | mat3 rows8-15 c4-7
    const uint32_t aoff = (uint32_t)((wr + (lm & 1) * 8 + lr) * XROWB + (lm >> 1) * 16);
    // B h0: mat0 n0 c0-3 | mat1 n0 c4-7 | mat2 n1 c0-3 | mat3 n1 c4-7
    const uint32_t b0off = (uint32_t)(WOFF + ((lm >> 1) * 8 + lr) * XROWB + (lm & 1) * 16);
    // B h1 (x2): mat0 n2 c0-3 | mat1 n2 c4-7   (lanes 0..15 used; pattern repeats)
    const uint32_t b1off = (uint32_t)(WOFF + (16 + lr) * XROWB + (lm & 1) * 16);

    // ---- stage-issue helper: X 256 float4 (4/thread), W 408 float4 ----
    const int xr = tid >> 4, xq = tid & 15;
    auto issue_stage = [&](int st, int c) {
        uint32_t xb = sb + st * STG;
        const float* xs = xtile + c * CK;
        #pragma unroll
        for (int i = 0; i < 4; i++) {
            int r = xr + i * 16;
            cp16(xb + r * XROWB + xq * 16, xs + (long)r * D + xq * 4);
        }
        const float4* wsrc = reinterpret_cast<const float4*>(g_Wsw + c * 24 * XROW);
        cp16(xb + WOFF + tid * 16, wsrc + tid);              // tid < 256 <= 408
        if (tid < W4 - 256) cp16(xb + WOFF + (tid + 256) * 16, wsrc + tid + 256);
    };

    // ---- prologue ----
    #pragma unroll
    for (int s = 0; s < S; s++) { issue_stage(s, s); CP_COMMIT(); }

    float acc0[4] = {0.f, 0.f, 0.f, 0.f};
    float acc1[4] = {0.f, 0.f, 0.f, 0.f};
    float ss0 = 0.0f, ss1 = 0.0f;

    // ---- mainloop ----
    for (int c = 0; c < NCHUNK; c++) {
        const int st = c & (S - 1);
        CP_WAIT3();
        __syncthreads();

        const uint32_t stb = sb + st * STG;
        const uint32_t aaddr = stb + aoff;
        if (h == 0) {
            const uint32_t baddr = stb + b0off;
            #pragma unroll
            for (int k0 = 0; k0 < 8; k0++) {
                uint32_t a0, a1, a2, a3, b0, b1, b2, b3;
                ldm_x4(a0, a1, a2, a3, aaddr + k0 * 32);
                ldm_x4(b0, b1, b2, b3, baddr + k0 * 32);
                mma_tf32(acc0[0], acc0[1], acc0[2], acc0[3], a0, a1, a2, a3, b0, b1);
                mma_tf32(acc1[0], acc1[1], acc1[2], acc1[3], a0, a1, a2, a3, b2, b3);
            }
        } else {
            const uint32_t baddr = stb + b1off;
            #pragma unroll
            for (int k0 = 0; k0 < 8; k0++) {
                uint32_t a0, a1, a2, a3, b0, b1;
                ldm_x4(a0, a1, a2, a3, aaddr + k0 * 32);
                ldm_x2(b0, b1, baddr + k0 * 32);
                mma_tf32(acc0[0], acc0[1], acc0[2], acc0[3], a0, a1, a2, a3, b0, b1);
                float f0 = __uint_as_float(a0), f1 = __uint_as_float(a1);
                float f2 = __uint_as_float(a2), f3 = __uint_as_float(a3);
                ss0 = fmaf(f0, f0, ss0); ss0 = fmaf(f2, f2, ss0);
                ss1 = fmaf(f1, f1, ss1); ss1 = fmaf(f3, f3, ss1);
            }
        }
        __syncthreads();
        const int nc = c + S;
        if (nc < NCHUNK) issue_stage(st, nc);
        CP_COMMIT();
    }

    // ---- dump fragments + sumsq to SMEM ----
    float* dots = sm + SM_DOTS / 4;
    if (h == 0) {
        #pragma unroll
        for (int n = 0; n < 2; n++) {
            const float* a = n ? acc1 : acc0;
            int col = n * 8 + 2 * cq;
            dots[(wr + gq) * DSTRIDE + col]         = a[0];
            dots[(wr + gq) * DSTRIDE + col + 1]     = a[1];
            dots[(wr + gq + 8) * DSTRIDE + col]     = a[2];
            dots[(wr + gq + 8) * DSTRIDE + col + 1] = a[3];
        }
    } else {
        int col = 16 + 2 * cq;
        dots[(wr + gq) * DSTRIDE + col]         = acc0[0];
        dots[(wr + gq) * DSTRIDE + col + 1]     = acc0[1];
        dots[(wr + gq + 8) * DSTRIDE + col]     = acc0[2];
        dots[(wr + gq + 8) * DSTRIDE + col + 1] = acc0[3];
        ss0 += __shfl_xor_sync(0xFFFFFFFFu, ss0, 1);
        ss0 += __shfl_xor_sync(0xFFFFFFFFu, ss0, 2);
        ss1 += __shfl_xor_sync(0xFFFFFFFFu, ss1, 1);
        ss1 += __shfl_xor_sync(0xFFFFFFFFu, ss1, 2);
        if (cq == 0) {
            dots[(wr + gq) * DSTRIDE + 24]     = ss0;
            dots[(wr + gq + 8) * DSTRIDE + 24] = ss1;
        }
    }
    __syncthreads();

    // ---- epilogue: one thread per row ----
    if (tid < TILE_M) {
        const float* dr = dots + tid * DSTRIDE;
        const long row = row0 + tid;
        const float ssq  = dr[24];
        const float rstd = rsqrtf(ssq * (1.0f / (float)D) + 1e-6f);
        const float ap  = __ldg(alpha_pre)  * rstd;
        const float aps = __ldg(alpha_post) * rstd;
        const float ar  = __ldg(alpha_res)  * rstd;

        float4 hp;
        hp.x = sigmoidf_(fmaf(ap, dr[0], __ldg(b_pre + 0)));
        hp.y = sigmoidf_(fmaf(ap, dr[1], __ldg(b_pre + 1)));
        hp.z = sigmoidf_(fmaf(ap, dr[2], __ldg(b_pre + 2)));
        hp.w = sigmoidf_(fmaf(ap, dr[3], __ldg(b_pre + 3)));
        reinterpret_cast<float4*>(out)[row] = hp;

        float4 ho;
        ho.x = 2.0f * sigmoidf_(fmaf(aps, dr[4], __ldg(b_post + 0)));
        ho.y = 2.0f * sigmoidf_(fmaf(aps, dr[5], __ldg(b_post + 1)));
        ho.z = 2.0f * sigmoidf_(fmaf(aps, dr[6], __ldg(b_post + 2)));
        ho.w = 2.0f * sigmoidf_(fmaf(aps, dr[7], __ldg(b_post + 3)));
        reinterpret_cast<float4*>(out)[ROWS + row] = ho;

        float P[16];
        #pragma unroll
        for (int m = 0; m < 16; m++) {
            float hh = fmaf(ar, dr[8 + m], __ldg(b_res + m));
            hh = fminf(fmaxf(hh, -15.0f), 15.0f);
            P[m] = __expf(hh);
        }
        #pragma unroll 1
        for (int it = 0; it < 20; it++) {
            #pragma unroll
            for (int j = 0; j < 4; j++) {
                float s = P[j] + P[4 + j] + P[8 + j] + P[12 + j];
                float inv = __fdividef(1.0f, s + 1e-6f);
                P[j] *= inv; P[4 + j] *= inv; P[8 + j] *= inv; P[12 + j] *= inv;
            }
            #pragma unroll
            for (int i = 0; i < 4; i++) {
                float s = P[i * 4] + P[i * 4 + 1] + P[i * 4 + 2] + P[i * 4 + 3];
                float inv = __fdividef(1.0f, s + 1e-6f);
                P[i * 4] *= inv; P[i * 4 + 1] *= inv; P[i * 4 + 2] *= inv; P[i * 4 + 3] *= inv;
            }
        }
        float4* ores = reinterpret_cast<float4*>(out) + 2 * ROWS + row * 4;
        ores[0] = make_float4(P[0],  P[1],  P[2],  P[3]);
        ores[1] = make_float4(P[4],  P[5],  P[6],  P[7]);
        ores[2] = make_float4(P[8],  P[9],  P[10], P[11]);
        ores[3] = make_float4(P[12], P[13], P[14], P[15]);
    }
}

// ---------------------------------------------------------------------------
extern "C" void kernel_launch(void* const* d_in, const int* in_sizes, int n_in,
                              void* d_out, int out_size) {
    const float* X      = (const float*)d_in[0];
    const float* g      = (const float*)d_in[1];
    const float* W_pre  = (const float*)d_in[2];
    const float* W_post = (const float*)d_in[3];
    const float* W_res  = (const float*)d_in[4];
    const float* b_pre  = (const float*)d_in[5];
    const float* b_post = (const float*)d_in[6];
    const float* b_res  = (const float*)d_in[7];
    const float* a_pre  = (const float*)d_in[8];
    const float* a_post = (const float*)d_in[9];
    const float* a_res  = (const float*)d_in[10];
    float* out = (float*)d_out;

    cudaFuncSetAttribute(mhc_main, cudaFuncAttributeMaxDynamicSharedMemorySize, SM_TOTAL);

    prep_w<<<(NCHUNK * 24 * XROW + 255) / 256, 256>>>(W_pre, W_post, W_res, g);
    mhc_main<<<NCTA, 256, SM_TOTAL>>>(X, b_pre, b_post, b_res,
                                      a_pre, a_post, a_res, out);
}

// round 9
// speedup vs baseline: 1.2215x; 1.2215x over previous
#include <cuda_runtime.h>
#include <cstdint>

#define DI __device__ __forceinline__

static constexpr int D       = 4096;
static constexpr int ROWS    = 16384;
static constexpr int TILE_M  = 128;
static constexpr int NCTA    = ROWS / TILE_M;    // 128
static constexpr int CK      = 64;               // k-floats per chunk
static constexpr int NCHUNK  = D / CK;           // 64
static constexpr int S       = 5;                // pipeline stages

static constexpr int XROW    = CK + 4;           // 68 floats (padded row)
static constexpr int XROWB   = XROW * 4;         // 272 bytes
static constexpr int XBYTES  = TILE_M * XROWB;   // 34816
static constexpr int WBYTES  = 24 * XROWB;       // 6528
static constexpr int STG     = XBYTES + WBYTES;  // 41344 per stage
static constexpr int WOFF    = XBYTES;
static constexpr int BAR_OFF = S * STG;          // 206720
static constexpr int DOTS_OFF = BAR_OFF + 128;   // 206848
static constexpr int DSTRIDE = 25;               // 24 dots + ssq
static constexpr int SM_TOTAL = DOTS_OFF + TILE_M * DSTRIDE * 4;  // 219648

static constexpr int NTHREADS   = 384;           // 8 consumer + 4 producer warps
static constexpr int NPROD_THR  = 128;
static constexpr int NCONS_THR  = 256;
static constexpr int W4         = 24 * XROW / 4; // 408 float4 per W chunk

// g-folded weight image, chunk-grouped: [NCHUNK][24][XROW]
__device__ __align__(16) float g_Wsw[NCHUNK * 24 * XROW];

// ---------------------------------------------------------------------------
DI uint32_t smem_u32(const void* p) {
    uint32_t a;
    asm("{ .reg .u64 t; cvta.to.shared.u64 t, %1; cvt.u32.u64 %0, t; }" : "=r"(a) : "l"(p));
    return a;
}
DI void cp16(uint32_t dst, const void* src) {
    asm volatile("cp.async.cg.shared.global [%0], [%1], 16;" :: "r"(dst), "l"(src) : "memory");
}
// NOTE: .noinc is load-bearing — the default form increments the pending count
// before arriving (net zero against the init count) and deadlocks this scheme.
#define CP_MBAR_ARRIVE_NOINC(addr) \
    asm volatile("cp.async.mbarrier.arrive.noinc.shared.b64 [%0];" :: "r"(addr) : "memory")
#define MBARRIER_INIT(addr, cnt) \
    asm volatile("mbarrier.init.shared.b64 [%0], %1;" :: "r"(addr), "r"(cnt) : "memory")
#define MBARRIER_ARRIVE(addr) \
    asm volatile("mbarrier.arrive.shared.b64 _, [%0];" :: "r"(addr) : "memory")

#define MBARRIER_WAIT_PARITY(mbar_addr, phase_parity) do {                               \
    uint32_t _mbar = (uint32_t)(mbar_addr);                                              \
    uint32_t _parity = (uint32_t)(phase_parity);                                         \
    uint32_t _done;                                                                      \
    asm volatile(                                                                        \
        "{\n\t.reg .pred p;\n\t"                                                         \
        "mbarrier.try_wait.parity.acquire.cta.shared::cta.b64 p, [%1], %2;\n\t"          \
        "selp.b32 %0, 1, 0, p;\n\t}"                                                     \
        : "=r"(_done) : "r"(_mbar), "r"(_parity) : "memory");                            \
    if (!_done) {                                                                        \
        asm volatile(                                                                    \
            "{\n\t.reg .pred P1;\n\t"                                                    \
            "WAIT_LOOP_%=:\n\t"                                                          \
            "mbarrier.try_wait.parity.acquire.cta.shared::cta.b64 P1, [%0], %1, 0x989680;\n\t" \
            "@P1 bra.uni WAIT_DONE_%=;\n\t"                                              \
            "bra.uni WAIT_LOOP_%=;\n\t"                                                  \
            "WAIT_DONE_%=:\n\t}"                                                         \
            :: "r"(_mbar), "r"(_parity) : "memory");                                     \
    }                                                                                    \
} while (0)

DI void ldm_x4(uint32_t& r0, uint32_t& r1, uint32_t& r2, uint32_t& r3, uint32_t addr) {
    asm volatile("ldmatrix.sync.aligned.m8n8.x4.shared.b16 {%0,%1,%2,%3}, [%4];"
                 : "=r"(r0), "=r"(r1), "=r"(r2), "=r"(r3) : "r"(addr));
}
DI void ldm_x2(uint32_t& r0, uint32_t& r1, uint32_t addr) {
    asm volatile("ldmatrix.sync.aligned.m8n8.x2.shared.b16 {%0,%1}, [%2];"
                 : "=r"(r0), "=r"(r1) : "r"(addr));
}
DI void mma_tf32(float& d0, float& d1, float& d2, float& d3,
                 uint32_t a0, uint32_t a1, uint32_t a2, uint32_t a3,
                 uint32_t b0, uint32_t b1) {
    asm volatile(
        "mma.sync.aligned.m16n8k8.row.col.f32.tf32.tf32.f32 "
        "{%0,%1,%2,%3}, {%4,%5,%6,%7}, {%8,%9}, {%0,%1,%2,%3};"
        : "+f"(d0), "+f"(d1), "+f"(d2), "+f"(d3)
        : "r"(a0), "r"(a1), "r"(a2), "r"(a3), "r"(b0), "r"(b1));
}
DI float sigmoidf_(float x) { return 1.0f / (1.0f + __expf(-x)); }

// ---------------------------------------------------------------------------
__global__ void prep_w(const float* __restrict__ Wpre, const float* __restrict__ Wpost,
                       const float* __restrict__ Wres, const float* __restrict__ g) {
    for (int idx = blockIdx.x * blockDim.x + threadIdx.x;
         idx < NCHUNK * 24 * XROW; idx += gridDim.x * blockDim.x) {
        int c   = idx / (24 * XROW);
        int rem = idx % (24 * XROW);
        int j   = rem / XROW;
        int k   = rem % XROW;
        float v = 0.0f;
        if (k < CK) {
            int kk = c * CK + k;
            float w = (j < 4)  ? Wpre[j * D + kk]
                    : (j < 8)  ? Wpost[(j - 4) * D + kk]
                    :            Wres[(j - 8) * D + kk];
            v = w * g[kk];
        }
        g_Wsw[idx] = v;
    }
}

// ---------------------------------------------------------------------------
// Warp-specialized: warps 0-7 consume (one 16-row m-tile each, 24 cols),
// warps 8-11 produce (cp.async -> 5-stage ring, mbarrier handshake).
// No __syncthreads in the mainloop.
// ---------------------------------------------------------------------------
__global__ void __launch_bounds__(NTHREADS, 1)
mhc_main(const float* __restrict__ X,
         const float* __restrict__ b_pre, const float* __restrict__ b_post,
         const float* __restrict__ b_res,
         const float* __restrict__ alpha_pre, const float* __restrict__ alpha_post,
         const float* __restrict__ alpha_res,
         float* __restrict__ out) {
    extern __shared__ char smem[];
    float* sm = reinterpret_cast<float*>(smem);
    const uint32_t sb = smem_u32(smem);
    const int tid  = threadIdx.x;
    const int wid  = tid >> 5, lane = tid & 31;
    const long row0 = (long)blockIdx.x * TILE_M;
    const float* xtile = X + row0 * D;

    if (tid == 0) {
        #pragma unroll
        for (int s = 0; s < S; s++) {
            MBARRIER_INIT(sb + BAR_OFF + s * 16,     NPROD_THR);  // full
            MBARRIER_INIT(sb + BAR_OFF + s * 16 + 8, NCONS_THR);  // empty
        }
    }
    __syncthreads();

    if (wid >= 8) {
        // ================= producer =================
        const int ptid = tid - NCONS_THR;       // 0..127
        int st = 0, ph = 0;
        for (int c = 0; c < NCHUNK; c++) {
            const uint32_t fullb  = sb + BAR_OFF + st * 16;
            if (c >= S) MBARRIER_WAIT_PARITY(fullb + 8, (ph - 1) & 1);
            const uint32_t xb = sb + st * STG;
            const float* xs = xtile + c * CK;
            #pragma unroll
            for (int i = 0; i < 16; i++) {
                int idx = ptid + i * 128;
                int r = idx >> 4, q = idx & 15;
                cp16(xb + r * XROWB + q * 16, xs + (long)r * D + q * 4);
            }
            const float4* wsrc = reinterpret_cast<const float4*>(g_Wsw + c * 24 * XROW);
            cp16(xb + WOFF + ptid * 16, wsrc + ptid);
            cp16(xb + WOFF + (ptid + 128) * 16, wsrc + ptid + 128);
            cp16(xb + WOFF + (ptid + 256) * 16, wsrc + ptid + 256);
            if (ptid < W4 - 384) cp16(xb + WOFF + (ptid + 384) * 16, wsrc + ptid + 384);
            CP_MBAR_ARRIVE_NOINC(fullb);
            if (++st == S) { st = 0; ph ^= 1; }
        }
    } else {
        // ================= consumer =================
        const int gq = lane >> 2, cq = lane & 3;
        const int wr = wid * 16;
        const int lm = lane >> 3, lr = lane & 7;
        const uint32_t aoff  = (uint32_t)((wr + (lm & 1) * 8 + lr) * XROWB + (lm >> 1) * 16);
        const uint32_t b0off = (uint32_t)(WOFF + ((lm >> 1) * 8 + lr) * XROWB + (lm & 1) * 16);
        const uint32_t b1off = (uint32_t)(WOFF + (16 + lr) * XROWB + (lm & 1) * 16);

        float acc0[4] = {0.f,0.f,0.f,0.f};
        float acc1[4] = {0.f,0.f,0.f,0.f};
        float acc2[4] = {0.f,0.f,0.f,0.f};
        float ss0 = 0.f, ss1 = 0.f;

        int st = 0, ph = 0;
        for (int c = 0; c < NCHUNK; c++) {
            const uint32_t fullb = sb + BAR_OFF + st * 16;
            MBARRIER_WAIT_PARITY(fullb, ph & 1);
            const uint32_t stb = sb + st * STG;
            const uint32_t aaddr = stb + aoff;
            const uint32_t baddr0 = stb + b0off;
            const uint32_t baddr1 = stb + b1off;
            #pragma unroll
            for (int k0 = 0; k0 < 8; k0++) {
                uint32_t a0, a1, a2, a3, b0, b1, b2, b3, c0, c1;
                ldm_x4(a0, a1, a2, a3, aaddr + k0 * 32);
                ldm_x4(b0, b1, b2, b3, baddr0 + k0 * 32);
                ldm_x2(c0, c1, baddr1 + k0 * 32);
                mma_tf32(acc0[0], acc0[1], acc0[2], acc0[3], a0, a1, a2, a3, b0, b1);
                mma_tf32(acc1[0], acc1[1], acc1[2], acc1[3], a0, a1, a2, a3, b2, b3);
                mma_tf32(acc2[0], acc2[1], acc2[2], acc2[3], a0, a1, a2, a3, c0, c1);
                float f0 = __uint_as_float(a0), f1 = __uint_as_float(a1);
                float f2 = __uint_as_float(a2), f3 = __uint_as_float(a3);
                ss0 = fmaf(f0, f0, ss0); ss0 = fmaf(f2, f2, ss0);
                ss1 = fmaf(f1, f1, ss1); ss1 = fmaf(f3, f3, ss1);
            }
            MBARRIER_ARRIVE(fullb + 8);
            if (++st == S) { st = 0; ph ^= 1; }
        }

        // dump fragments + sumsq
        float* dots = sm + DOTS_OFF / 4;
        const float* accs[3] = {acc0, acc1, acc2};
        #pragma unroll
        for (int n = 0; n < 3; n++) {
            int col = n * 8 + 2 * cq;
            dots[(wr + gq) * DSTRIDE + col]         = accs[n][0];
            dots[(wr + gq) * DSTRIDE + col + 1]     = accs[n][1];
            dots[(wr + gq + 8) * DSTRIDE + col]     = accs[n][2];
            dots[(wr + gq + 8) * DSTRIDE + col + 1] = accs[n][3];
        }
        ss0 += __shfl_xor_sync(0xFFFFFFFFu, ss0, 1);
        ss0 += __shfl_xor_sync(0xFFFFFFFFu, ss0, 2);
        ss1 += __shfl_xor_sync(0xFFFFFFFFu, ss1, 1);
        ss1 += __shfl_xor_sync(0xFFFFFFFFu, ss1, 2);
        if (cq == 0) {
            dots[(wr + gq) * DSTRIDE + 24]     = ss0;
            dots[(wr + gq + 8) * DSTRIDE + 24] = ss1;
        }
    }
    __syncthreads();

    // ---- epilogue: one thread per row ----
    if (tid < TILE_M) {
        const float* dr = sm + DOTS_OFF / 4 + tid * DSTRIDE;
        const long row = row0 + tid;
        const float ssq  = dr[24];
        const float rstd = rsqrtf(ssq * (1.0f / (float)D) + 1e-6f);
        const float ap  = __ldg(alpha_pre)  * rstd;
        const float aps = __ldg(alpha_post) * rstd;
        const float ar  = __ldg(alpha_res)  * rstd;

        float4 hp;
        hp.x = sigmoidf_(fmaf(ap, dr[0], __ldg(b_pre + 0)));
        hp.y = sigmoidf_(fmaf(ap, dr[1], __ldg(b_pre + 1)));
        hp.z = sigmoidf_(fmaf(ap, dr[2], __ldg(b_pre + 2)));
        hp.w = sigmoidf_(fmaf(ap, dr[3], __ldg(b_pre + 3)));
        reinterpret_cast<float4*>(out)[row] = hp;

        float4 ho;
        ho.x = 2.0f * sigmoidf_(fmaf(aps, dr[4], __ldg(b_post + 0)));
        ho.y = 2.0f * sigmoidf_(fmaf(aps, dr[5], __ldg(b_post + 1)));
        ho.z = 2.0f * sigmoidf_(fmaf(aps, dr[6], __ldg(b_post + 2)));
        ho.w = 2.0f * sigmoidf_(fmaf(aps, dr[7], __ldg(b_post + 3)));
        reinterpret_cast<float4*>(out)[ROWS + row] = ho;

        float P[16];
        #pragma unroll
        for (int m = 0; m < 16; m++) {
            float hh = fmaf(ar, dr[8 + m], __ldg(b_res + m));
            hh = fminf(fmaxf(hh, -15.0f), 15.0f);
            P[m] = __expf(hh);
        }
        #pragma unroll 1
        for (int it = 0; it < 20; it++) {
            #pragma unroll
            for (int j = 0; j < 4; j++) {
                float s = P[j] + P[4 + j] + P[8 + j] + P[12 + j];
                float inv = __fdividef(1.0f, s + 1e-6f);
                P[j] *= inv; P[4 + j] *= inv; P[8 + j] *= inv; P[12 + j] *= inv;
            }
            #pragma unroll
            for (int i = 0; i < 4; i++) {
                float s = P[i * 4] + P[i * 4 + 1] + P[i * 4 + 2] + P[i * 4 + 3];
                float inv = __fdividef(1.0f, s + 1e-6f);
                P[i * 4] *= inv; P[i * 4 + 1] *= inv; P[i * 4 + 2] *= inv; P[i * 4 + 3] *= inv;
            }
        }
        float4* ores = reinterpret_cast<float4*>(out) + 2 * ROWS + row * 4;
        ores[0] = make_float4(P[0],  P[1],  P[2],  P[3]);
        ores[1] = make_float4(P[4],  P[5],  P[6],  P[7]);
        ores[2] = make_float4(P[8],  P[9],  P[10], P[11]);
        ores[3] = make_float4(P[12], P[13], P[14], P[15]);
    }
}

// ---------------------------------------------------------------------------
extern "C" void kernel_launch(void* const* d_in, const int* in_sizes, int n_in,
                              void* d_out, int out_size) {
    const float* X      = (const float*)d_in[0];
    const float* g      = (const float*)d_in[1];
    const float* W_pre  = (const float*)d_in[2];
    const float* W_post = (const float*)d_in[3];
    const float* W_res  = (const float*)d_in[4];
    const float* b_pre  = (const float*)d_in[5];
    const float* b_post = (const float*)d_in[6];
    const float* b_res  = (const float*)d_in[7];
    const float* a_pre  = (const float*)d_in[8];
    const float* a_post = (const float*)d_in[9];
    const float* a_res  = (const float*)d_in[10];
    float* out = (float*)d_out;

    cudaFuncSetAttribute(mhc_main, cudaFuncAttributeMaxDynamicSharedMemorySize, SM_TOTAL);

    prep_w<<<(NCHUNK * 24 * XROW + 255) / 256, 256>>>(W_pre, W_post, W_res, g);
    mhc_main<<<NCTA, NTHREADS, SM_TOTAL>>>(X, b_pre, b_post, b_res,
                                           a_pre, a_post, a_res, out);
}